// round 13
// baseline (speedup 1.0000x reference)
#include <cuda_runtime.h>

// TransD forward, simplified (eye is identity, RD==ED):
//   h_out = renorm(rp) * <renorm(hp), renorm(hv)> + renorm(hv)
//   rv_out = renorm(rv)
//   t_out = renorm(rp) * <renorm(tp), renorm(tv)> + renorm(tv)
//
// Best-measured config (R5): two warps per sample
//   side 0: gathers hv,hp,rp,rv -> h_out + rv_out
//   side 1: gathers tv,tp,rp    -> t_out
// Low front-batched MLP (3-4 loads) minimizes cross-CTA L1tex-queue spread.

#define NB 8192
#define DV 32u  // float4s per 128-float row
#define FULL 0xffffffffu

__device__ __forceinline__ float dot4(float4 a, float4 b) {
    return a.x * b.x + a.y * b.y + a.z * b.z + a.w * b.w;
}

__device__ __forceinline__ float rscale(float sumsq) {
    float n = sqrtf(sumsq);
    return (n > 1.0f) ? (1.0f / (n + 1e-7f)) : 1.0f;
}

__device__ __forceinline__ void st_cs(float4* p, float4 v) {
    asm volatile("st.global.cs.v4.f32 [%0], {%1,%2,%3,%4};"
                 :: "l"(p), "f"(v.x), "f"(v.y), "f"(v.z), "f"(v.w) : "memory");
}

__global__ __launch_bounds__(256) void transd_kernel(
    const float4* __restrict__ ee,   // entity_emb      [ENT*32]
    const float4* __restrict__ eep,  // entity_emb_p    [ENT*32]
    const float4* __restrict__ re,   // relation_emb    [REL*32]
    const float4* __restrict__ rep,  // relation_emb_p  [REL*32]
    const int* __restrict__ h,
    const int* __restrict__ r,
    const int* __restrict__ t,
    float4* __restrict__ out)        // [3 * NB * 32]
{
    int gw = (blockIdx.x * blockDim.x + threadIdx.x) >> 5;
    unsigned lane = threadIdx.x & 31u;
    int s = gw >> 1;        // sample
    int side = gw & 1;      // 0 = h-side (+rv), 1 = t-side
    if (s >= NB) return;

    int ri = __ldg(&r[s]);
    int ei = side ? __ldg(&t[s]) : __ldg(&h[s]);

    unsigned oe  = (unsigned)ei * DV + lane;
    unsigned orr = (unsigned)ri * DV + lane;

    // gathers up front (3 or 4 per warp)
    float4 ev = __ldg(ee  + oe);    // hv or tv
    float4 ep = __ldg(eep + oe);    // hp or tp
    float4 rp = __ldg(rep + orr);
    float4 rv;
    if (!side) rv = __ldg(re + orr);

    // 4 reductions: 0:|ev|^2 1:|ep|^2 2:|rp|^2 3:<ep,ev>
    float p0 = dot4(ev, ev);
    float p1 = dot4(ep, ep);
    float p2 = dot4(rp, rp);
    float p3 = dot4(ep, ev);

    // stage A: reduce each within groups of 4 lanes
    p0 += __shfl_xor_sync(FULL, p0, 1); p0 += __shfl_xor_sync(FULL, p0, 2);
    p1 += __shfl_xor_sync(FULL, p1, 1); p1 += __shfl_xor_sync(FULL, p1, 2);
    p2 += __shfl_xor_sync(FULL, p2, 1); p2 += __shfl_xor_sync(FULL, p2, 2);
    p3 += __shfl_xor_sync(FULL, p3, 1); p3 += __shfl_xor_sync(FULL, p3, 2);

    // stage B: lane (l&3) carries value q through xor 4, 8, 16
    unsigned q = lane & 3u;
    float w = (q & 2u) ? ((q & 1u) ? p3 : p2) : ((q & 1u) ? p1 : p0);
    w += __shfl_xor_sync(FULL, w, 4);
    w += __shfl_xor_sync(FULL, w, 8);
    w += __shfl_xor_sync(FULL, w, 16);

    float s_ev = __shfl_sync(FULL, w, 0);
    float s_ep = __shfl_sync(FULL, w, 1);
    float s_rp = __shfl_sync(FULL, w, 2);
    float d    = __shfl_sync(FULL, w, 3);

    // rv norm (side 0 only; warp-uniform branch)
    float s_rv = 0.0f;
    if (!side) {
        float pr = dot4(rv, rv);
        pr += __shfl_xor_sync(FULL, pr, 1);
        pr += __shfl_xor_sync(FULL, pr, 2);
        pr += __shfl_xor_sync(FULL, pr, 4);
        pr += __shfl_xor_sync(FULL, pr, 8);
        pr += __shfl_xor_sync(FULL, pr, 16);
        s_rv = pr;
    }

    float c_ev = rscale(s_ev);
    float a = rscale(s_rp) * (d * rscale(s_ep) * c_ev);

    unsigned base = (unsigned)s * DV + lane;

    float4 o;
    o.x = rp.x * a + ev.x * c_ev;
    o.y = rp.y * a + ev.y * c_ev;
    o.z = rp.z * a + ev.z * c_ev;
    o.w = rp.w * a + ev.w * c_ev;
    st_cs(&out[side ? (2u * NB * DV + base) : base], o);

    if (!side) {
        float c_rv = rscale(s_rv);
        o.x = rv.x * c_rv; o.y = rv.y * c_rv;
        o.z = rv.z * c_rv; o.w = rv.w * c_rv;
        st_cs(&out[NB * DV + base], o);
    }
}

extern "C" void kernel_launch(void* const* d_in, const int* in_sizes, int n_in,
                              void* d_out, int out_size) {
    const float4* ee  = (const float4*)d_in[0];
    const float4* eep = (const float4*)d_in[1];
    const float4* re  = (const float4*)d_in[2];
    const float4* rep = (const float4*)d_in[3];
    const int* h = (const int*)d_in[4];
    const int* r = (const int*)d_in[5];
    const int* t = (const int*)d_in[6];

    // 2 warps per sample -> 16384 warps -> 2048 blocks of 256 threads
    int blocks = (2 * NB * 32 + 255) / 256;
    transd_kernel<<<blocks, 256>>>(ee, eep, re, rep, h, r, t, (float4*)d_out);
}

// round 14
// speedup vs baseline: 1.2657x; 1.2657x over previous
#include <cuda_runtime.h>

// TransD forward, simplified (eye is identity, RD==ED):
//   h_out = renorm(rp) * <renorm(hp), renorm(hv)> + renorm(hv)
//   rv_out = renorm(rv)
//   t_out = renorm(rp) * <renorm(tp), renorm(tv)> + renorm(tv)
//
// Two warps per sample: side 0 computes h_out + rv_out, side 1 computes t_out.
// Shorter per-warp chains (3-4 gathers, 4-5 reductions) for better latency hiding.

#define NB 8192
#define DV 32  // float4s per 128-float row
#define FULL 0xffffffffu

__device__ __forceinline__ float dot4(float4 a, float4 b) {
    return a.x * b.x + a.y * b.y + a.z * b.z + a.w * b.w;
}

__device__ __forceinline__ float rscale(float sumsq) {
    float n = sqrtf(sumsq);
    return (n > 1.0f) ? (1.0f / (n + 1e-7f)) : 1.0f;
}

__device__ __forceinline__ void st_cs(float4* p, float4 v) {
    asm volatile("st.global.cs.v4.f32 [%0], {%1,%2,%3,%4};"
                 :: "l"(p), "f"(v.x), "f"(v.y), "f"(v.z), "f"(v.w) : "memory");
}

__global__ __launch_bounds__(256) void transd_kernel(
    const float4* __restrict__ ee,   // entity_emb      [ENT*32]
    const float4* __restrict__ eep,  // entity_emb_p    [ENT*32]
    const float4* __restrict__ re,   // relation_emb    [REL*32]
    const float4* __restrict__ rep,  // relation_emb_p  [REL*32]
    const int* __restrict__ h,
    const int* __restrict__ r,
    const int* __restrict__ t,
    float4* __restrict__ out)        // [3 * NB * 32]
{
    int gw = (blockIdx.x * blockDim.x + threadIdx.x) >> 5;
    int lane = threadIdx.x & 31;
    int s = gw >> 1;        // sample
    int side = gw & 1;      // 0 = h-side (+rv), 1 = t-side
    if (s >= NB) return;

    int ri = r[s];
    int ei = side ? t[s] : h[s];

    // gathers up front
    float4 ev = __ldg(&ee [(long)ei * DV + lane]);   // hv or tv
    float4 ep = __ldg(&eep[(long)ei * DV + lane]);   // hp or tp
    float4 rp = __ldg(&rep[(long)ri * DV + lane]);
    float4 rv;
    if (!side) rv = __ldg(&re[(long)ri * DV + lane]);

    // 4 (or 5) reductions
    float p0 = dot4(ev, ev);
    float p1 = dot4(ep, ep);
    float p2 = dot4(rp, rp);
    float p3 = dot4(ep, ev);

    // stage A: reduce within groups of 4 lanes
    p0 += __shfl_xor_sync(FULL, p0, 1); p0 += __shfl_xor_sync(FULL, p0, 2);
    p1 += __shfl_xor_sync(FULL, p1, 1); p1 += __shfl_xor_sync(FULL, p1, 2);
    p2 += __shfl_xor_sync(FULL, p2, 1); p2 += __shfl_xor_sync(FULL, p2, 2);
    p3 += __shfl_xor_sync(FULL, p3, 1); p3 += __shfl_xor_sync(FULL, p3, 2);

    // stage B: lane (l&3) carries value q through xor 4, 8, 16
    int q = lane & 3;
    float w = (q & 2) ? ((q & 1) ? p3 : p2) : ((q & 1) ? p1 : p0);
    w += __shfl_xor_sync(FULL, w, 4);
    w += __shfl_xor_sync(FULL, w, 8);
    w += __shfl_xor_sync(FULL, w, 16);

    float s_ev = __shfl_sync(FULL, w, 0);
    float s_ep = __shfl_sync(FULL, w, 1);
    float s_rp = __shfl_sync(FULL, w, 2);
    float d    = __shfl_sync(FULL, w, 3);

    // rv norm (side 0 only; warp-uniform branch)
    float s_rv = 0.0f;
    if (!side) {
        float pr = dot4(rv, rv);
        pr += __shfl_xor_sync(FULL, pr, 1);
        pr += __shfl_xor_sync(FULL, pr, 2);
        pr += __shfl_xor_sync(FULL, pr, 4);
        pr += __shfl_xor_sync(FULL, pr, 8);
        pr += __shfl_xor_sync(FULL, pr, 16);
        s_rv = pr;
    }

    float c_ev = rscale(s_ev);
    float a = rscale(s_rp) * (d * rscale(s_ep) * c_ev);

    long base = (long)s * DV + lane;

    float4 o;
    o.x = rp.x * a + ev.x * c_ev;
    o.y = rp.y * a + ev.y * c_ev;
    o.z = rp.z * a + ev.z * c_ev;
    o.w = rp.w * a + ev.w * c_ev;
    st_cs(&out[side ? (2L * NB * DV + base) : base], o);

    if (!side) {
        float c_rv = rscale(s_rv);
        o.x = rv.x * c_rv; o.y = rv.y * c_rv;
        o.z = rv.z * c_rv; o.w = rv.w * c_rv;
        st_cs(&out[(long)NB * DV + base], o);
    }
}

extern "C" void kernel_launch(void* const* d_in, const int* in_sizes, int n_in,
                              void* d_out, int out_size) {
    const float4* ee  = (const float4*)d_in[0];
    const float4* eep = (const float4*)d_in[1];
    const float4* re  = (const float4*)d_in[2];
    const float4* rep = (const float4*)d_in[3];
    const int* h = (const int*)d_in[4];
    const int* r = (const int*)d_in[5];
    const int* t = (const int*)d_in[6];

    // 2 warps per sample -> 16384 warps -> 2048 blocks of 256 threads
    int blocks = (2 * NB * 32 + 255) / 256;
    transd_kernel<<<blocks, 256>>>(ee, eep, re, rep, h, r, t, (float4*)d_out);
}